// round 2
// baseline (speedup 1.0000x reference)
#include <cuda_runtime.h>
#include <cstdint>
#include <cstddef>

#define HEADS 12
#define HD    64
#define DIMM  768
#define BB    8
#define NN    1024
#define TOK   8192            // BB*NN
#define SCALEF 0.125f         // HD^-0.5

// Scratch (module-static device memory; no runtime allocation).
// g_qkv[z][which(q/k/v)][b][h][n][d]
__device__ float g_qkv[2][3][BB][HEADS][NN][HD];   // ~302 MB
// g_o[z][token][dim] — attention outputs, contiguous for the proj GEMM
__device__ float g_o[2][TOK][DIMM];                // ~50 MB

__device__ __forceinline__ uint32_t f2tf(float x) {
    uint32_t r;
    asm("cvt.rna.tf32.f32 %0, %1;" : "=r"(r) : "f"(x));
    return r;
}

// D += A(16x8 tf32, row) * B(8x8 tf32, col)
__device__ __forceinline__ void mma8(float d[4],
                                     uint32_t a0, uint32_t a1, uint32_t a2, uint32_t a3,
                                     uint32_t b0, uint32_t b1) {
    asm volatile(
        "mma.sync.aligned.m16n8k8.row.col.f32.tf32.tf32.f32 "
        "{%0,%1,%2,%3}, {%4,%5,%6,%7}, {%8,%9}, {%0,%1,%2,%3};\n"
        : "+f"(d[0]), "+f"(d[1]), "+f"(d[2]), "+f"(d[3])
        : "r"(a0), "r"(a1), "r"(a2), "r"(a3), "r"(b0), "r"(b1));
}

// ---------------------------------------------------------------------------
// Generic C = A @ W^T tf32 GEMM. Block tile 128x128, BK=32, 256 threads.
// MODE 0: qkv projection.  A = x (z=0) or x2 (z=1), [8192,768]; W=[2304,768].
//         Epilogue scatters into g_qkv[z][which][b][h][n][d].
// MODE 1: output projection. A = g_o flattened [16384,768]; W=[768,768]+bias.
//         Writes d_out directly.
// All dims are multiples of 128 -> no bounds checks.
// ---------------------------------------------------------------------------
template<int MODE>
__global__ __launch_bounds__(256)
void gemm_tf32(const float* __restrict__ A0, const float* __restrict__ A1,
               const float* __restrict__ W,  const float* __restrict__ bias,
               float* __restrict__ out)
{
    __shared__ uint32_t As[128][36];   // [m][k], stride 36 -> bank (4m+k)%32
    __shared__ uint32_t Bs[128][36];   // [n][k]

    const int K  = DIMM;
    const int n0 = blockIdx.x * 128;
    const int m0 = blockIdx.y * 128;

    const float* A;
    if (MODE == 0) A = blockIdx.z ? A1 : A0;
    else           A = &g_o[0][0][0];

    const int tid  = threadIdx.x;
    const int srow = tid >> 3;          // 0..31
    const int scol = (tid & 7) * 4;     // 0..28
    const int warp = tid >> 5, lane = tid & 31;
    const int g = lane >> 2, t = lane & 3;
    const int wm = (warp & 1) * 64;     // warp m-offset
    const int wn = (warp >> 1) * 32;    // warp n-offset

    float acc[4][4][4];
    #pragma unroll
    for (int i = 0; i < 4; i++)
        #pragma unroll
        for (int j = 0; j < 4; j++) {
            acc[i][j][0] = 0.f; acc[i][j][1] = 0.f;
            acc[i][j][2] = 0.f; acc[i][j][3] = 0.f;
        }

    for (int k0 = 0; k0 < K; k0 += 32) {
        #pragma unroll
        for (int i = 0; i < 4; i++) {
            int r = srow + i * 32;
            float4 v = *(const float4*)(A + (size_t)(m0 + r) * K + k0 + scol);
            As[r][scol + 0] = f2tf(v.x); As[r][scol + 1] = f2tf(v.y);
            As[r][scol + 2] = f2tf(v.z); As[r][scol + 3] = f2tf(v.w);
            float4 w = *(const float4*)(W + (size_t)(n0 + r) * K + k0 + scol);
            Bs[r][scol + 0] = f2tf(w.x); Bs[r][scol + 1] = f2tf(w.y);
            Bs[r][scol + 2] = f2tf(w.z); Bs[r][scol + 3] = f2tf(w.w);
        }
        __syncthreads();

        #pragma unroll
        for (int kk = 0; kk < 32; kk += 8) {
            uint32_t af[4][4], bf[4][2];
            #pragma unroll
            for (int mi = 0; mi < 4; mi++) {
                int m = wm + mi * 16;
                af[mi][0] = As[m + g][kk + t];
                af[mi][1] = As[m + g + 8][kk + t];
                af[mi][2] = As[m + g][kk + t + 4];
                af[mi][3] = As[m + g + 8][kk + t + 4];
            }
            #pragma unroll
            for (int ni = 0; ni < 4; ni++) {
                int n = wn + ni * 8 + g;
                bf[ni][0] = Bs[n][kk + t];
                bf[ni][1] = Bs[n][kk + t + 4];
            }
            #pragma unroll
            for (int mi = 0; mi < 4; mi++)
                #pragma unroll
                for (int ni = 0; ni < 4; ni++)
                    mma8(acc[mi][ni],
                         af[mi][0], af[mi][1], af[mi][2], af[mi][3],
                         bf[ni][0], bf[ni][1]);
        }
        __syncthreads();
    }

    if (MODE == 1) {
        #pragma unroll
        for (int mi = 0; mi < 4; mi++) {
            int m = m0 + wm + mi * 16 + g;
            #pragma unroll
            for (int ni = 0; ni < 4; ni++) {
                int n = n0 + wn + ni * 8 + 2 * t;
                float b0 = bias[n], b1 = bias[n + 1];
                *(float2*)(out + (size_t)m * DIMM + n) =
                    make_float2(acc[mi][ni][0] + b0, acc[mi][ni][1] + b1);
                *(float2*)(out + (size_t)(m + 8) * DIMM + n) =
                    make_float2(acc[mi][ni][2] + b0, acc[mi][ni][3] + b1);
            }
        }
    } else {
        const int z = blockIdx.z;
        #pragma unroll
        for (int mi = 0; mi < 4; mi++) {
            int m = m0 + wm + mi * 16 + g;      // token index; m and m+8 stay in same batch
            int b  = m >> 10, nn = m & 1023;
            #pragma unroll
            for (int ni = 0; ni < 4; ni++) {
                int n = n0 + wn + ni * 8 + 2 * t;
                int which = n / DIMM;
                int rem   = n - which * DIMM;
                int h = rem >> 6, d = rem & 63; // 2t even, d and d+1 in same head
                *(float2*)&g_qkv[z][which][b][h][nn][d] =
                    make_float2(acc[mi][ni][0], acc[mi][ni][1]);
                *(float2*)&g_qkv[z][which][b][h][nn + 8][d] =
                    make_float2(acc[mi][ni][2], acc[mi][ni][3]);
            }
        }
    }
}

// ---------------------------------------------------------------------------
// Flash attention: grid (16 q-tiles, 96 bh, 2 branches), 128 threads (4 warps).
// Q tile 64x64 held in registers (fragments); loop over 16 K/V tiles of 64.
// Q for BOTH branches comes from x (branch index only selects K/V).
// P bounces through shared (Ks buffer reused) because the tf32 C-fragment
// layout does not match the A-fragment layout.
// ---------------------------------------------------------------------------
__global__ __launch_bounds__(128)
void flash_attn()
{
    __shared__ uint32_t Ks[64 * 68];   // K tile / Q staging / P tile. stride 68 -> (4m+k)%32
    __shared__ uint32_t Vs[64 * 72];   // V tile [key][d], stride 72 -> (8k+n)%32

    const int qt = blockIdx.x;
    const int bh = blockIdx.y;
    const int z  = blockIdx.z;
    const int b  = bh / HEADS, h = bh - b * HEADS;

    const float* Qg = &g_qkv[0][0][b][h][qt * 64][0];
    const float* Kg = &g_qkv[z][1][b][h][0][0];
    const float* Vg = &g_qkv[z][2][b][h][0][0];

    const int tid = threadIdx.x, warp = tid >> 5, lane = tid & 31;
    const int g = lane >> 2, t = lane & 3;
    const int wr = warp * 16;           // warp row offset within 64
    const int srow = tid >> 4;          // 0..7 staging row
    const int scol = (tid & 15) * 4;    // 0..60

    // Stage Q (pre-scaled by SCALE: power of two, exact) then pull fragments.
    #pragma unroll
    for (int i = 0; i < 8; i++) {
        int r = srow + i * 8;
        float4 v = *(const float4*)(Qg + r * HD + scol);
        Ks[r * 68 + scol + 0] = f2tf(v.x * SCALEF);
        Ks[r * 68 + scol + 1] = f2tf(v.y * SCALEF);
        Ks[r * 68 + scol + 2] = f2tf(v.z * SCALEF);
        Ks[r * 68 + scol + 3] = f2tf(v.w * SCALEF);
    }
    __syncthreads();
    uint32_t qa[8][4];
    #pragma unroll
    for (int ks = 0; ks < 8; ks++) {
        qa[ks][0] = Ks[(wr + g) * 68     + ks * 8 + t];
        qa[ks][1] = Ks[(wr + g + 8) * 68 + ks * 8 + t];
        qa[ks][2] = Ks[(wr + g) * 68     + ks * 8 + t + 4];
        qa[ks][3] = Ks[(wr + g + 8) * 68 + ks * 8 + t + 4];
    }
    __syncthreads();

    float O[8][4];
    #pragma unroll
    for (int i = 0; i < 8; i++) { O[i][0] = 0.f; O[i][1] = 0.f; O[i][2] = 0.f; O[i][3] = 0.f; }
    float rm0 = -1e30f, rm1 = -1e30f, rl0 = 0.f, rl1 = 0.f;

    for (int kt = 0; kt < 16; kt++) {
        // Stage K and V tiles (converted to tf32 bits).
        #pragma unroll
        for (int i = 0; i < 8; i++) {
            int r = srow + i * 8;
            float4 kv = *(const float4*)(Kg + (size_t)(kt * 64 + r) * HD + scol);
            Ks[r * 68 + scol + 0] = f2tf(kv.x);
            Ks[r * 68 + scol + 1] = f2tf(kv.y);
            Ks[r * 68 + scol + 2] = f2tf(kv.z);
            Ks[r * 68 + scol + 3] = f2tf(kv.w);
            float4 vv = *(const float4*)(Vg + (size_t)(kt * 64 + r) * HD + scol);
            Vs[r * 72 + scol + 0] = f2tf(vv.x);
            Vs[r * 72 + scol + 1] = f2tf(vv.y);
            Vs[r * 72 + scol + 2] = f2tf(vv.z);
            Vs[r * 72 + scol + 3] = f2tf(vv.w);
        }
        __syncthreads();

        // S = (Q*scale) @ K^T   (warp: 16 rows x 64 keys)
        float S[8][4];
        #pragma unroll
        for (int i = 0; i < 8; i++) { S[i][0] = 0.f; S[i][1] = 0.f; S[i][2] = 0.f; S[i][3] = 0.f; }
        #pragma unroll
        for (int ni = 0; ni < 8; ni++) {
            #pragma unroll
            for (int ks = 0; ks < 8; ks++) {
                uint32_t b0 = Ks[(ni * 8 + g) * 68 + ks * 8 + t];
                uint32_t b1 = Ks[(ni * 8 + g) * 68 + ks * 8 + t + 4];
                mma8(S[ni], qa[ks][0], qa[ks][1], qa[ks][2], qa[ks][3], b0, b1);
            }
        }

        // Online softmax. Thread owns rows (wr+g) and (wr+g+8); quad shares a row.
        float mx0 = -1e30f, mx1 = -1e30f;
        #pragma unroll
        for (int ni = 0; ni < 8; ni++) {
            mx0 = fmaxf(mx0, fmaxf(S[ni][0], S[ni][1]));
            mx1 = fmaxf(mx1, fmaxf(S[ni][2], S[ni][3]));
        }
        mx0 = fmaxf(mx0, __shfl_xor_sync(0xffffffffu, mx0, 1));
        mx0 = fmaxf(mx0, __shfl_xor_sync(0xffffffffu, mx0, 2));
        mx1 = fmaxf(mx1, __shfl_xor_sync(0xffffffffu, mx1, 1));
        mx1 = fmaxf(mx1, __shfl_xor_sync(0xffffffffu, mx1, 2));
        float nm0 = fmaxf(rm0, mx0), nm1 = fmaxf(rm1, mx1);
        float al0 = __expf(rm0 - nm0), al1 = __expf(rm1 - nm1);
        float s0 = 0.f, s1 = 0.f;
        #pragma unroll
        for (int ni = 0; ni < 8; ni++) {
            S[ni][0] = __expf(S[ni][0] - nm0); s0 += S[ni][0];
            S[ni][1] = __expf(S[ni][1] - nm0); s0 += S[ni][1];
            S[ni][2] = __expf(S[ni][2] - nm1); s1 += S[ni][2];
            S[ni][3] = __expf(S[ni][3] - nm1); s1 += S[ni][3];
        }
        s0 += __shfl_xor_sync(0xffffffffu, s0, 1);
        s0 += __shfl_xor_sync(0xffffffffu, s0, 2);
        s1 += __shfl_xor_sync(0xffffffffu, s1, 1);
        s1 += __shfl_xor_sync(0xffffffffu, s1, 2);
        rl0 = rl0 * al0 + s0; rl1 = rl1 * al1 + s1;
        rm0 = nm0; rm1 = nm1;
        #pragma unroll
        for (int ni = 0; ni < 8; ni++) {
            O[ni][0] *= al0; O[ni][1] *= al0; O[ni][2] *= al1; O[ni][3] *= al1;
        }

        // Bounce P through shared (reuse Ks) to re-fragment C-layout -> A-layout.
        __syncthreads();   // everyone done reading K tile
        #pragma unroll
        for (int ni = 0; ni < 8; ni++) {
            Ks[(wr + g) * 68     + ni * 8 + 2 * t]     = f2tf(S[ni][0]);
            Ks[(wr + g) * 68     + ni * 8 + 2 * t + 1] = f2tf(S[ni][1]);
            Ks[(wr + g + 8) * 68 + ni * 8 + 2 * t]     = f2tf(S[ni][2]);
            Ks[(wr + g + 8) * 68 + ni * 8 + 2 * t + 1] = f2tf(S[ni][3]);
        }
        __syncwarp();      // each warp reads back only its own 16 rows
        uint32_t pa[8][4];
        #pragma unroll
        for (int ks = 0; ks < 8; ks++) {
            pa[ks][0] = Ks[(wr + g) * 68     + ks * 8 + t];
            pa[ks][1] = Ks[(wr + g + 8) * 68 + ks * 8 + t];
            pa[ks][2] = Ks[(wr + g) * 68     + ks * 8 + t + 4];
            pa[ks][3] = Ks[(wr + g + 8) * 68 + ks * 8 + t + 4];
        }

        // O += P @ V
        #pragma unroll
        for (int ni = 0; ni < 8; ni++) {
            #pragma unroll
            for (int ks = 0; ks < 8; ks++) {
                uint32_t b0 = Vs[(ks * 8 + t) * 72     + ni * 8 + g];
                uint32_t b1 = Vs[(ks * 8 + t + 4) * 72 + ni * 8 + g];
                mma8(O[ni], pa[ks][0], pa[ks][1], pa[ks][2], pa[ks][3], b0, b1);
            }
        }
        __syncthreads();   // before next iteration overwrites Ks/Vs
    }

    // Normalize and write o in [token][H*D] layout (proj-GEMM-ready).
    float inv0 = 1.f / rl0, inv1 = 1.f / rl1;
    int row = b * NN + qt * 64 + wr + g;
    #pragma unroll
    for (int ni = 0; ni < 8; ni++) {
        int c = h * HD + ni * 8 + 2 * t;
        *(float2*)&g_o[z][row][c]     = make_float2(O[ni][0] * inv0, O[ni][1] * inv0);
        *(float2*)&g_o[z][row + 8][c] = make_float2(O[ni][2] * inv1, O[ni][3] * inv1);
    }
}

// ---------------------------------------------------------------------------
// kernel_launch: 3 graph-capturable launches on the default stream.
// Inputs per metadata: x, x2, qkv_w, proj_w, proj_b (all float32).
// Output: [out1; out2] = [2,8,1024,768] float32.
// ---------------------------------------------------------------------------
extern "C" void kernel_launch(void* const* d_in, const int* in_sizes, int n_in,
                              void* d_out, int out_size)
{
    const float* x      = (const float*)d_in[0];
    const float* x2     = (const float*)d_in[1];
    const float* qkv_w  = (const float*)d_in[2];
    const float* proj_w = (const float*)d_in[3];
    const float* proj_b = (const float*)d_in[4];
    float* out = (float*)d_out;

    // QKV for x (z=0, full 2304 cols) and x2 (z=1; q2 computed but unused)
    gemm_tf32<0><<<dim3(18, 64, 2), 256>>>(x, x2, qkv_w, nullptr, nullptr);

    // Two-branch flash attention
    flash_attn<<<dim3(16, 96, 2), 128>>>();

    // Fused projection over [o1; o2] -> d_out (+bias)
    gemm_tf32<1><<<dim3(6, 128, 1), 256>>>(nullptr, nullptr, proj_w, proj_b, out);
}

// round 3
// speedup vs baseline: 1.1379x; 1.1379x over previous
#include <cuda_runtime.h>
#include <cstdint>
#include <cstddef>

#define HEADS 12
#define HD    64
#define DIMM  768
#define BB    8
#define NN    1024
#define TOK   8192
#define SCALEF 0.125f

// ---- static device scratch (no runtime allocation) ----
__device__ float g_qkv[2][3][BB][HEADS][NN][HD]; // tf32-rounded q/k/v (q pre-scaled)
__device__ float g_o[2][TOK][DIMM];              // attention out (tf32-rounded)
__device__ float g_x[2][TOK][DIMM];              // tf32-rounded x / x2
__device__ float g_w[3*DIMM][DIMM];              // tf32-rounded qkv_w
__device__ float g_pw[DIMM][DIMM];               // tf32-rounded proj_w

__device__ __forceinline__ uint32_t f2tf(float x) {
    uint32_t r; asm("cvt.rna.tf32.f32 %0, %1;" : "=r"(r) : "f"(x)); return r;
}
__device__ __forceinline__ float tfbits(float x) { return __uint_as_float(f2tf(x)); }

__device__ __forceinline__ void mma8(float d[4],
                                     uint32_t a0, uint32_t a1, uint32_t a2, uint32_t a3,
                                     uint32_t b0, uint32_t b1) {
    asm volatile(
        "mma.sync.aligned.m16n8k8.row.col.f32.tf32.tf32.f32 "
        "{%0,%1,%2,%3}, {%4,%5,%6,%7}, {%8,%9}, {%0,%1,%2,%3};\n"
        : "+f"(d[0]), "+f"(d[1]), "+f"(d[2]), "+f"(d[3])
        : "r"(a0), "r"(a1), "r"(a2), "r"(a3), "r"(b0), "r"(b1));
}
__device__ __forceinline__ void cp16(uint32_t dst, const void* src) {
    asm volatile("cp.async.cg.shared.global [%0], [%1], 16;" :: "r"(dst), "l"(src));
}
#define CP_COMMIT() asm volatile("cp.async.commit_group;")
#define CP_WAIT1()  asm volatile("cp.async.wait_group 1;")
#define CP_WAIT0()  asm volatile("cp.async.wait_group 0;")

// ---- pre-round all inputs to tf32 ----
__global__ void round_all(const float4* __restrict__ x,  const float4* __restrict__ x2,
                          const float4* __restrict__ qw, const float4* __restrict__ pw) {
    const int C1 = 1572864, C2 = 3145728, C3 = 3588096, C4 = 3735552;
    float4* dx0 = (float4*)&g_x[0][0][0];
    float4* dx1 = (float4*)&g_x[1][0][0];
    float4* dw  = (float4*)&g_w[0][0];
    float4* dpw = (float4*)&g_pw[0][0];
    for (int i = blockIdx.x * blockDim.x + threadIdx.x; i < C4;
         i += gridDim.x * blockDim.x) {
        const float4* s; float4* d; int j;
        if (i < C1)      { s = x;  d = dx0; j = i; }
        else if (i < C2) { s = x2; d = dx1; j = i - C1; }
        else if (i < C3) { s = qw; d = dw;  j = i - C2; }
        else             { s = pw; d = dpw; j = i - C3; }
        float4 v = s[j];
        v.x = tfbits(v.x); v.y = tfbits(v.y); v.z = tfbits(v.z); v.w = tfbits(v.w);
        d[j] = v;
    }
}

// ---------------------------------------------------------------------------
// C = A @ W^T. Block 128(M)x256(N), BK=32, 256 thr, 8 warps of 64x64.
// 2-stage cp.async. Stage layout (floats): A[128][36] then B[256][36].
// MODE 0: A=g_x[z], W=g_w -> g_qkv (rounded; q scaled). z=1 skips q (bx<3).
// MODE 1: A=g_o, W=g_pw, +bias -> out.
// ---------------------------------------------------------------------------
template<int MODE>
__global__ __launch_bounds__(256, 1)
void gemm2(const float* __restrict__ bias, float* __restrict__ out)
{
    extern __shared__ uint32_t sh[];
    const int z = blockIdx.z;
    if (MODE == 0 && z == 1 && blockIdx.x < 3) return;   // q2 unused
    const int n0 = blockIdx.x * 256;
    const int m0 = blockIdx.y * 128;
    const float* A  = (MODE == 0) ? &g_x[z][0][0] : &g_o[0][0][0];
    const float* Wp = (MODE == 0) ? &g_w[0][0]    : &g_pw[0][0];

    const int tid = threadIdx.x, warp = tid >> 5, lane = tid & 31;
    const int g = lane >> 2, t = lane & 3;
    const int wm = (warp & 1) * 64, wn = (warp >> 1) * 64;
    const uint32_t shb = (uint32_t)__cvta_generic_to_shared(sh);

    float acc[4][8][4];
    #pragma unroll
    for (int i = 0; i < 4; i++)
        #pragma unroll
        for (int j = 0; j < 8; j++)
            acc[i][j][0] = acc[i][j][1] = acc[i][j][2] = acc[i][j][3] = 0.f;

    auto issue = [&](int it, int s) {
        const uint32_t base = shb + (uint32_t)s * 13824u * 4u;
        const int k0 = it * 32;
        #pragma unroll
        for (int i = 0; i < 4; i++) {                       // A: 1024 chunks
            int id = tid + i * 256, row = id >> 3, c = id & 7;
            cp16(base + (uint32_t)(row * 36 + c * 4) * 4u,
                 A + (size_t)(m0 + row) * DIMM + k0 + c * 4);
        }
        #pragma unroll
        for (int i = 0; i < 8; i++) {                       // B: 2048 chunks
            int id = tid + i * 256, row = id >> 3, c = id & 7;
            cp16(base + (uint32_t)(4608 + row * 36 + c * 4) * 4u,
                 Wp + (size_t)(n0 + row) * DIMM + k0 + c * 4);
        }
    };
    issue(0, 0); CP_COMMIT();
    issue(1, 1); CP_COMMIT();

    const int nIt = DIMM / 32;  // 24
    for (int it = 0; it < nIt; it++) {
        if (it == nIt - 1) { CP_WAIT0(); } else { CP_WAIT1(); }
        __syncthreads();
        const uint32_t* sA = sh + (it & 1) * 13824;
        const uint32_t* sB = sA + 4608;
        #pragma unroll
        for (int kk = 0; kk < 32; kk += 8) {
            uint32_t af[4][4], bf[8][2];
            #pragma unroll
            for (int mi = 0; mi < 4; mi++) {
                int m = wm + mi * 16;
                af[mi][0] = sA[(m + g) * 36 + kk + t];
                af[mi][1] = sA[(m + g + 8) * 36 + kk + t];
                af[mi][2] = sA[(m + g) * 36 + kk + t + 4];
                af[mi][3] = sA[(m + g + 8) * 36 + kk + t + 4];
            }
            #pragma unroll
            for (int ni = 0; ni < 8; ni++) {
                int n = wn + ni * 8 + g;
                bf[ni][0] = sB[n * 36 + kk + t];
                bf[ni][1] = sB[n * 36 + kk + t + 4];
            }
            #pragma unroll
            for (int mi = 0; mi < 4; mi++)
                #pragma unroll
                for (int ni = 0; ni < 8; ni++)
                    mma8(acc[mi][ni], af[mi][0], af[mi][1], af[mi][2], af[mi][3],
                         bf[ni][0], bf[ni][1]);
        }
        __syncthreads();
        if (it + 2 < nIt) { issue(it + 2, it & 1); CP_COMMIT(); }
    }

    if (MODE == 1) {
        #pragma unroll
        for (int mi = 0; mi < 4; mi++) {
            int m = m0 + wm + mi * 16 + g;
            #pragma unroll
            for (int ni = 0; ni < 8; ni++) {
                int n = n0 + wn + ni * 8 + 2 * t;
                float b0 = bias[n], b1 = bias[n + 1];
                *(float2*)(out + (size_t)m * DIMM + n) =
                    make_float2(acc[mi][ni][0] + b0, acc[mi][ni][1] + b1);
                *(float2*)(out + (size_t)(m + 8) * DIMM + n) =
                    make_float2(acc[mi][ni][2] + b0, acc[mi][ni][3] + b1);
            }
        }
    } else {
        #pragma unroll
        for (int mi = 0; mi < 4; mi++) {
            int m = m0 + wm + mi * 16 + g;
            int bb_ = m >> 10, nn_ = m & 1023;
            #pragma unroll
            for (int ni = 0; ni < 8; ni++) {
                int n = n0 + wn + ni * 8 + 2 * t;
                int which = n / DIMM;
                int rem = n - which * DIMM;
                int hh = rem >> 6, d = rem & 63;
                float s = (which == 0) ? SCALEF : 1.0f;
                *(float2*)&g_qkv[z][which][bb_][hh][nn_][d] =
                    make_float2(tfbits(acc[mi][ni][0] * s), tfbits(acc[mi][ni][1] * s));
                *(float2*)&g_qkv[z][which][bb_][hh][nn_ + 8][d] =
                    make_float2(tfbits(acc[mi][ni][2] * s), tfbits(acc[mi][ni][3] * s));
            }
        }
    }
}

// ---------------------------------------------------------------------------
// Flash attention. Grid (16 q-tiles, 96 bh, 2 z), 128 thr (4 warps x 16 rows).
// K/V cp.async double-buffered. Q frags direct from gmem (pre-scaled tf32).
// P C-frag -> A-frag via shuffles (no shared bounce, no extra barriers).
// Stage layout (words): K[64][68] then V[64][72]; stage = 8960 words.
// ---------------------------------------------------------------------------
__global__ __launch_bounds__(128)
void flash2()
{
    extern __shared__ uint32_t sh[];
    const int qt = blockIdx.x, bh = blockIdx.y, z = blockIdx.z;
    const int b = bh / HEADS, h = bh - b * HEADS;
    const float* Qg = &g_qkv[0][0][b][h][qt * 64][0];
    const float* Kg = &g_qkv[z][1][b][h][0][0];
    const float* Vg = &g_qkv[z][2][b][h][0][0];

    const int tid = threadIdx.x, warp = tid >> 5, lane = tid & 31;
    const int g = lane >> 2, t = lane & 3;
    const int wr = warp * 16;
    const uint32_t shb = (uint32_t)__cvta_generic_to_shared(sh);

    auto issue = [&](int kt, int s) {
        const uint32_t base = shb + (uint32_t)s * 8960u * 4u;
        #pragma unroll
        for (int i = 0; i < 8; i++) {
            int id = tid + i * 128, row = id >> 4, c = id & 15;
            cp16(base + (uint32_t)(row * 68 + c * 4) * 4u,
                 Kg + (size_t)(kt * 64 + row) * HD + c * 4);
            cp16(base + (uint32_t)(4352 + row * 72 + c * 4) * 4u,
                 Vg + (size_t)(kt * 64 + row) * HD + c * 4);
        }
    };
    issue(0, 0); CP_COMMIT();
    issue(1, 1); CP_COMMIT();

    uint32_t qa[8][4];
    #pragma unroll
    for (int ks = 0; ks < 8; ks++) {
        qa[ks][0] = __float_as_uint(Qg[(wr + g) * HD + ks * 8 + t]);
        qa[ks][1] = __float_as_uint(Qg[(wr + g + 8) * HD + ks * 8 + t]);
        qa[ks][2] = __float_as_uint(Qg[(wr + g) * HD + ks * 8 + t + 4]);
        qa[ks][3] = __float_as_uint(Qg[(wr + g + 8) * HD + ks * 8 + t + 4]);
    }

    float O[8][4];
    #pragma unroll
    for (int i = 0; i < 8; i++) { O[i][0] = O[i][1] = O[i][2] = O[i][3] = 0.f; }
    float rm0 = -1e30f, rm1 = -1e30f, rl0 = 0.f, rl1 = 0.f;
    const int srcA = (lane & 28) | (t >> 1);
    const int srcB = srcA + 2;

    for (int kt = 0; kt < 16; kt++) {
        if (kt == 15) { CP_WAIT0(); } else { CP_WAIT1(); }
        __syncthreads();
        const uint32_t* Ks = sh + (kt & 1) * 8960;
        const uint32_t* Vs = Ks + 4352;

        float S[8][4];
        #pragma unroll
        for (int i = 0; i < 8; i++) { S[i][0] = S[i][1] = S[i][2] = S[i][3] = 0.f; }
        #pragma unroll
        for (int ni = 0; ni < 8; ni++)
            #pragma unroll
            for (int ks = 0; ks < 8; ks++)
                mma8(S[ni], qa[ks][0], qa[ks][1], qa[ks][2], qa[ks][3],
                     Ks[(ni * 8 + g) * 68 + ks * 8 + t],
                     Ks[(ni * 8 + g) * 68 + ks * 8 + t + 4]);

        float mx0 = -1e30f, mx1 = -1e30f;
        #pragma unroll
        for (int ni = 0; ni < 8; ni++) {
            mx0 = fmaxf(mx0, fmaxf(S[ni][0], S[ni][1]));
            mx1 = fmaxf(mx1, fmaxf(S[ni][2], S[ni][3]));
        }
        mx0 = fmaxf(mx0, __shfl_xor_sync(0xffffffffu, mx0, 1));
        mx0 = fmaxf(mx0, __shfl_xor_sync(0xffffffffu, mx0, 2));
        mx1 = fmaxf(mx1, __shfl_xor_sync(0xffffffffu, mx1, 1));
        mx1 = fmaxf(mx1, __shfl_xor_sync(0xffffffffu, mx1, 2));
        float nm0 = fmaxf(rm0, mx0), nm1 = fmaxf(rm1, mx1);
        float al0 = __expf(rm0 - nm0), al1 = __expf(rm1 - nm1);
        float s0 = 0.f, s1 = 0.f;
        #pragma unroll
        for (int ni = 0; ni < 8; ni++) {
            S[ni][0] = __expf(S[ni][0] - nm0); s0 += S[ni][0];
            S[ni][1] = __expf(S[ni][1] - nm0); s0 += S[ni][1];
            S[ni][2] = __expf(S[ni][2] - nm1); s1 += S[ni][2];
            S[ni][3] = __expf(S[ni][3] - nm1); s1 += S[ni][3];
        }
        s0 += __shfl_xor_sync(0xffffffffu, s0, 1);
        s0 += __shfl_xor_sync(0xffffffffu, s0, 2);
        s1 += __shfl_xor_sync(0xffffffffu, s1, 1);
        s1 += __shfl_xor_sync(0xffffffffu, s1, 2);
        rl0 = rl0 * al0 + s0; rl1 = rl1 * al1 + s1;
        rm0 = nm0; rm1 = nm1;
        #pragma unroll
        for (int ni = 0; ni < 8; ni++) {
            O[ni][0] *= al0; O[ni][1] *= al0; O[ni][2] *= al1; O[ni][3] *= al1;
        }

        // C-frag -> A-frag: pa[ks] = P(rows g/g+8, cols 8ks+t / +4) via shuffles
        uint32_t pa[8][4];
        #pragma unroll
        for (int ks = 0; ks < 8; ks++) {
            uint32_t e0 = f2tf(S[ks][0]), e1 = f2tf(S[ks][1]);
            uint32_t e2 = f2tf(S[ks][2]), e3 = f2tf(S[ks][3]);
            uint32_t xA0 = __shfl_sync(0xffffffffu, e0, srcA);
            uint32_t xA1 = __shfl_sync(0xffffffffu, e1, srcA);
            uint32_t xA2 = __shfl_sync(0xffffffffu, e2, srcA);
            uint32_t xA3 = __shfl_sync(0xffffffffu, e3, srcA);
            uint32_t xB0 = __shfl_sync(0xffffffffu, e0, srcB);
            uint32_t xB1 = __shfl_sync(0xffffffffu, e1, srcB);
            uint32_t xB2 = __shfl_sync(0xffffffffu, e2, srcB);
            uint32_t xB3 = __shfl_sync(0xffffffffu, e3, srcB);
            pa[ks][0] = (t & 1) ? xA1 : xA0;
            pa[ks][1] = (t & 1) ? xA3 : xA2;
            pa[ks][2] = (t & 1) ? xB1 : xB0;
            pa[ks][3] = (t & 1) ? xB3 : xB2;
        }

        #pragma unroll
        for (int ni = 0; ni < 8; ni++)
            #pragma unroll
            for (int ks = 0; ks < 8; ks++)
                mma8(O[ni], pa[ks][0], pa[ks][1], pa[ks][2], pa[ks][3],
                     Vs[(ks * 8 + t) * 72 + ni * 8 + g],
                     Vs[(ks * 8 + t + 4) * 72 + ni * 8 + g]);

        __syncthreads();
        if (kt + 2 < 16) { issue(kt + 2, kt & 1); CP_COMMIT(); }
    }

    float inv0 = 1.f / rl0, inv1 = 1.f / rl1;
    int row = b * NN + qt * 64 + wr + g;
    #pragma unroll
    for (int ni = 0; ni < 8; ni++) {
        int c = h * HD + ni * 8 + 2 * t;
        *(float2*)&g_o[z][row][c] =
            make_float2(tfbits(O[ni][0] * inv0), tfbits(O[ni][1] * inv0));
        *(float2*)&g_o[z][row + 8][c] =
            make_float2(tfbits(O[ni][2] * inv1), tfbits(O[ni][3] * inv1));
    }
}

// ---------------------------------------------------------------------------
extern "C" void kernel_launch(void* const* d_in, const int* in_sizes, int n_in,
                              void* d_out, int out_size)
{
    const float* x      = (const float*)d_in[0];
    const float* x2     = (const float*)d_in[1];
    const float* qkv_w  = (const float*)d_in[2];
    const float* proj_w = (const float*)d_in[3];
    const float* proj_b = (const float*)d_in[4];
    float* out = (float*)d_out;

    cudaFuncSetAttribute(gemm2<0>, cudaFuncAttributeMaxDynamicSharedMemorySize, 110592);
    cudaFuncSetAttribute(gemm2<1>, cudaFuncAttributeMaxDynamicSharedMemorySize, 110592);
    cudaFuncSetAttribute(flash2,   cudaFuncAttributeMaxDynamicSharedMemorySize, 71680);

    round_all<<<2048, 256>>>((const float4*)x, (const float4*)x2,
                             (const float4*)qkv_w, (const float4*)proj_w);
    gemm2<0><<<dim3(9, 64, 2), 256, 110592>>>(nullptr, nullptr);
    flash2<<<dim3(16, 96, 2), 128, 71680>>>();
    gemm2<1><<<dim3(3, 128, 1), 256, 110592>>>(proj_b, out);
}